// round 8
// baseline (speedup 1.0000x reference)
#include <cuda_runtime.h>
#include <math.h>

#define BB 32
#define TT 1024
#define II 512
#define HH 512
#define G4 2048      // 4*H
#define GRID_P 128   // persistent CTAs (<=148 -> co-resident, deadlock-free)

typedef unsigned long long u64t;

// ---- packed fp32x2 helpers (Blackwell FFMA2) ----
__device__ __forceinline__ u64t ffma2(u64t a, u64t b, u64t c) {
    u64t d;
    asm("fma.rn.f32x2 %0, %1, %2, %3;" : "=l"(d) : "l"(a), "l"(b), "l"(c));
    return d;
}
__device__ __forceinline__ u64t pack2(float x, float y) {
    u64t d;
    asm("mov.b64 %0, {%1, %2};" : "=l"(d) : "f"(x), "f"(y));
    return d;
}
__device__ __forceinline__ float2 unpack2(u64t v) {
    float2 r;
    asm("mov.b64 {%0, %1}, %2;" : "=f"(r.x), "=f"(r.y) : "l"(v));
    return r;
}
// L2-coherent 16B load (L1 is stale across CTAs; REQUIRED for h double-buffer)
__device__ __forceinline__ void ldcg2(const float* p, u64t& a, u64t& b) {
    asm volatile("ld.global.cg.v2.u64 {%0,%1}, [%2];" : "=l"(a), "=l"(b) : "l"(p));
}

// ---------------- scratch (static device globals; no allocation) ----------------
__device__ float    g_xpre[(size_t)BB * TT * G4];   // [B][T][4H]  256 MB
__device__ float    g_hT[2][HH * BB];               // double-buffered h^T [k][b]
__device__ unsigned g_bar_count;
__device__ unsigned g_bar_phase;

// ---------------- Kernel 1: x_pre = x @ [Wii|Wif|Wio|Wig] + bias ----------------
// (unchanged from the 6181us version)
__global__ __launch_bounds__(256) void gemm_x_kernel(
    const float* __restrict__ X,
    const float* __restrict__ Wii, const float* __restrict__ Wif,
    const float* __restrict__ Wio, const float* __restrict__ Wig,
    const float* __restrict__ bi, const float* __restrict__ bf,
    const float* __restrict__ bo, const float* __restrict__ bg,
    const float* __restrict__ h0,
    float* __restrict__ xpre)
{
    const int mtile = blockIdx.x;          // 0..255
    const int gtile = blockIdx.y;          // 0..15
    const int gate  = gtile >> 2;
    const int j0    = (gtile & 3) * 128;

    if (mtile == 0 && gtile == 0) {
        for (int i = threadIdx.x; i < BB * HH; i += 256) {
            int b = i >> 9;
            int j = i & 511;
            g_hT[0][j * BB + b] = h0[i];
        }
        if (threadIdx.x == 0) { g_bar_count = 0; g_bar_phase = 0; }
    }

    const float* W    = (gate == 0) ? Wii : (gate == 1) ? Wif : (gate == 2) ? Wio : Wig;
    const float* bias = (gate == 0) ? bi  : (gate == 1) ? bf  : (gate == 2) ? bo  : bg;

    __shared__ float As[2][8][132];
    __shared__ float Bs[2][8][128];

    const int tid = threadIdx.x;
    const int tx = tid & 15;
    const int ty = tid >> 4;
    const int m0 = mtile * 128;

    const int a_row = tid >> 1;
    const int a_k   = (tid & 1) * 4;
    const int b_k = tid >> 5;
    const int b_n = (tid & 31) * 4;

    u64t acc2[8][4];
#pragma unroll
    for (int i = 0; i < 8; i++)
#pragma unroll
        for (int j = 0; j < 4; j++) acc2[i][j] = 0ull;

    {
        float4 av = *(const float4*)(X + (size_t)(m0 + a_row) * 512 + a_k);
        As[0][a_k + 0][a_row] = av.x;
        As[0][a_k + 1][a_row] = av.y;
        As[0][a_k + 2][a_row] = av.z;
        As[0][a_k + 3][a_row] = av.w;
        float4 bv = *(const float4*)(W + (size_t)b_k * 512 + j0 + b_n);
        *(float4*)&Bs[0][b_k][b_n] = bv;
    }
    __syncthreads();

    for (int k0 = 0; k0 < 512; k0 += 8) {
        const int cur = (k0 >> 3) & 1;
        const int nxt = cur ^ 1;

        float4 av, bv;
        const bool more = (k0 + 8 < 512);
        if (more) {
            av = *(const float4*)(X + (size_t)(m0 + a_row) * 512 + k0 + 8 + a_k);
            bv = *(const float4*)(W + (size_t)(k0 + 8 + b_k) * 512 + j0 + b_n);
        }

#pragma unroll
        for (int kk = 0; kk < 8; kk++) {
            float4 a0 = *(const float4*)&As[cur][kk][ty * 8];
            float4 a1 = *(const float4*)&As[cur][kk][ty * 8 + 4];
            u64t arr[8];
            arr[0] = pack2(a0.x, a0.x); arr[1] = pack2(a0.y, a0.y);
            arr[2] = pack2(a0.z, a0.z); arr[3] = pack2(a0.w, a0.w);
            arr[4] = pack2(a1.x, a1.x); arr[5] = pack2(a1.y, a1.y);
            arr[6] = pack2(a1.z, a1.z); arr[7] = pack2(a1.w, a1.w);
            ulonglong2 bb0 = *(const ulonglong2*)&Bs[cur][kk][tx * 8];
            ulonglong2 bb1 = *(const ulonglong2*)&Bs[cur][kk][tx * 8 + 4];
            u64t br2[4];
            br2[0] = bb0.x; br2[1] = bb0.y; br2[2] = bb1.x; br2[3] = bb1.y;
#pragma unroll
            for (int i = 0; i < 8; i++)
#pragma unroll
                for (int j = 0; j < 4; j++)
                    acc2[i][j] = ffma2(arr[i], br2[j], acc2[i][j]);
        }

        if (more) {
            As[nxt][a_k + 0][a_row] = av.x;
            As[nxt][a_k + 1][a_row] = av.y;
            As[nxt][a_k + 2][a_row] = av.z;
            As[nxt][a_k + 3][a_row] = av.w;
            *(float4*)&Bs[nxt][b_k][b_n] = bv;
        }
        __syncthreads();
    }

#pragma unroll
    for (int i = 0; i < 8; i++) {
        const size_t m = (size_t)(m0 + ty * 8 + i);
        float* dst = xpre + m * G4 + gate * 512 + j0 + tx * 8;
        float4 o0, o1;
        float2 p0 = unpack2(acc2[i][0]);
        float2 p1 = unpack2(acc2[i][1]);
        float2 p2 = unpack2(acc2[i][2]);
        float2 p3 = unpack2(acc2[i][3]);
        o0.x = p0.x + bias[j0 + tx * 8 + 0];
        o0.y = p0.y + bias[j0 + tx * 8 + 1];
        o0.z = p1.x + bias[j0 + tx * 8 + 2];
        o0.w = p1.y + bias[j0 + tx * 8 + 3];
        o1.x = p2.x + bias[j0 + tx * 8 + 4];
        o1.y = p2.y + bias[j0 + tx * 8 + 5];
        o1.z = p3.x + bias[j0 + tx * 8 + 6];
        o1.w = p3.y + bias[j0 + tx * 8 + 7];
        *(float4*)dst       = o0;
        *(float4*)(dst + 4) = o1;
    }
}

// ---------------- Kernel 2: persistent recurrence (512 threads / 16 warps) -------
// 128 CTAs. CTA owns 4 h-cols jc..jc+3 -> 16 gate-cols.
// Warp w (0..15): k-slice [w*32, w*32+32). Lane = gco*4 + bq:
//   bq  (0..3): 8 batches [bq*8, bq*8+8) (4 FFMA2 b-pairs)
//   gco (0..7): 2 gate-cols {2gco, 2gco+1}
// Per k per lane: ONE LDS.128 of pre-splatted weight pairs + 8 FFMA2.
// 4 warps/SMSP -> depth-1 h-prefetch (4-k chunks) is latency-covered.
//
// SMEM layout (floats):
#define PS_STRIDE 33
#define SH_W  0                             // w splat [k][gc][2]  512*32 = 16384
#define SH_PS (SH_W  + 512*32)              // partials [w*16+gc][33] 256*33 = 8448
#define SH_XS (SH_PS + 256*PS_STRIDE)       // xpre [q][b][jj]     4*32*4 = 512
#define SH_C  (SH_XS + 4*32*4)              // cell [jj][b]        128
#define SH_HO (SH_C  + 4*32)                // h out [b][jj]       128
#define SH_TOTAL_FLOATS (SH_HO + 32*4)

extern __shared__ float smem_p[];

__global__ __launch_bounds__(512, 1) void lstm_persist_kernel(
    const float* __restrict__ xpre,
    const float* __restrict__ Whi, const float* __restrict__ Whf,
    const float* __restrict__ Who, const float* __restrict__ Whg,
    const float* __restrict__ c0,
    float* __restrict__ out,
    int write_tail)
{
    float* sh_w  = smem_p + SH_W;
    float* sh_ps = smem_p + SH_PS;
    float* sh_xs = smem_p + SH_XS;
    float* sh_c  = smem_p + SH_C;
    float* sh_ho = smem_p + SH_HO;

    const int tid  = threadIdx.x;
    const int lane = tid & 31;
    const int w    = tid >> 5;              // 0..15
    const int jc   = blockIdx.x * 4;        // h-column base

    const int bq  = lane & 3;
    const int gco = lane >> 2;               // 0..7

    // ---- one-time: weight slice SPLATTED: sh_w[k*32 + gc*2 + {0,1}] = W[k][gc]
    for (int e = tid; e < 512 * 16; e += 512) {
        int k   = e >> 4;
        int gcl = e & 15;
        int q   = gcl >> 2;
        int jj  = gcl & 3;
        const float* Wq = (q == 0) ? Whi : (q == 1) ? Whf : (q == 2) ? Who : Whg;
        float wv = Wq[(size_t)k * HH + jc + jj];
        sh_w[k * 32 + gcl * 2 + 0] = wv;
        sh_w[k * 32 + gcl * 2 + 1] = wv;
    }
    if (tid < 128) {
        int jj = tid >> 5;
        int b  = tid & 31;
        sh_c[jj * 32 + b] = c0[b * HH + jc + jj];
    }
    __syncthreads();

    const int kb = w * 32;                   // warp k-slice base (32 k's)

    const int g_jj = tid >> 5;               // gates mapping (tid<128)
    const int g_b  = tid & 31;
    const int x_b = tid >> 2;                // xpre mapping (tid<128)
    const int x_q = tid & 3;

    float4 xnext;
    if (tid < 128)
        xnext = *(const float4*)(xpre + ((size_t)x_b * TT + 0) * G4 + x_q * 512 + jc);

    for (int t = 0; t < TT; ++t) {
        const float* hT_r = g_hT[t & 1];
        float*       hT_w = g_hT[(t + 1) & 1];

        // ---- commit staged xpre; prefetch next ----
        if (tid < 128) {
            *(float4*)(sh_xs + (x_q * 32 + x_b) * 4) = xnext;
            if (t + 1 < TT)
                xnext = *(const float4*)(xpre + ((size_t)x_b * TT + t + 1) * G4 + x_q * 512 + jc);
        }

        // ---- recurrent GEMM slice ----
        // acc[g][bp]: gate-col g of pair x b-pair bp, over lane's 32 k's
        u64t acc[2][4];
#pragma unroll
        for (int g = 0; g < 2; g++)
#pragma unroll
            for (int bp = 0; bp < 4; bp++) acc[g][bp] = 0ull;

        const float* hlane = hT_r + (size_t)kb * BB + bq * 8;
        const float* wrow  = sh_w + kb * 32 + gco * 4;   // 2 splatted pairs per k

        u64t bufA[16], bufB[16];
        // prefetch chunk 0 (k offsets 0..3): 4 k x 8 batches
#pragma unroll
        for (int j = 0; j < 4; j++) {
            ldcg2(hlane + j * BB,     bufA[j * 4 + 0], bufA[j * 4 + 1]);
            ldcg2(hlane + j * BB + 4, bufA[j * 4 + 2], bufA[j * 4 + 3]);
        }

#pragma unroll
        for (int c = 0; c < 8; c++) {
            u64t* cur = (c & 1) ? bufB : bufA;
            u64t* nxt = (c & 1) ? bufA : bufB;
            if (c < 7) {
                const float* hp2 = hlane + (size_t)(c + 1) * 4 * BB;
#pragma unroll
                for (int j = 0; j < 4; j++) {
                    ldcg2(hp2 + j * BB,     nxt[j * 4 + 0], nxt[j * 4 + 1]);
                    ldcg2(hp2 + j * BB + 4, nxt[j * 4 + 2], nxt[j * 4 + 3]);
                }
            }
#pragma unroll
            for (int j = 0; j < 4; j++) {
                const int kk = c * 4 + j;
                ulonglong2 wv = *(const ulonglong2*)(wrow + kk * 32);
                u64t ws0 = wv.x, ws1 = wv.y;       // 2 splatted gate-col weights
                u64t h0 = cur[j * 4 + 0];
                u64t h1 = cur[j * 4 + 1];
                u64t h2 = cur[j * 4 + 2];
                u64t h3 = cur[j * 4 + 3];
                acc[0][0] = ffma2(h0, ws0, acc[0][0]);
                acc[1][0] = ffma2(h0, ws1, acc[1][0]);
                acc[0][1] = ffma2(h1, ws0, acc[0][1]);
                acc[1][1] = ffma2(h1, ws1, acc[1][1]);
                acc[0][2] = ffma2(h2, ws0, acc[0][2]);
                acc[1][2] = ffma2(h2, ws1, acc[1][2]);
                acc[0][3] = ffma2(h3, ws0, acc[0][3]);
                acc[1][3] = ffma2(h3, ws1, acc[1][3]);
            }
        }

        // ---- write partials (scalar stores; padded rows avoid conflicts) ----
#pragma unroll
        for (int g = 0; g < 2; g++) {
            float* ps = sh_ps + (w * 16 + gco * 2 + g) * PS_STRIDE + bq * 8;
#pragma unroll
            for (int bp = 0; bp < 4; bp++) {
                float2 v = unpack2(acc[g][bp]);
                ps[bp * 2 + 0] = v.x;
                ps[bp * 2 + 1] = v.y;
            }
        }
        __syncthreads();

        // ---- gates + state update (128 threads: jj x b) ----
        if (tid < 128) {
            const int jj = g_jj, b = g_b;
            float v[4];
#pragma unroll
            for (int q = 0; q < 4; q++) {
                float s = sh_xs[(q * 32 + b) * 4 + jj];
                const int gc = q * 4 + jj;
#pragma unroll
                for (int ws16 = 0; ws16 < 16; ws16++)
                    s += sh_ps[(ws16 * 16 + gc) * PS_STRIDE + b];
                v[q] = s;
            }
            float it = 1.0f / (1.0f + expf(-v[0]));
            float ft = 1.0f / (1.0f + expf(-v[1]));
            float ot = 1.0f / (1.0f + expf(-v[2]));
            float gt = tanhf(v[3]);
            float cn = ft * sh_c[jj * 32 + b] + it * gt;
            float hn = ot * tanhf(cn);
            sh_c[jj * 32 + b] = cn;
            sh_ho[b * 4 + jj] = hn;
            hT_w[(jc + jj) * BB + b] = hn;     // coalesced 128B per jj
        }
        __syncthreads();

        // ---- arrival, output write, poll (warp 0) ----
        if (tid == 0) {
            __threadfence();
            unsigned a = atomicAdd(&g_bar_count, 1u);
            if (a == (unsigned)(GRID_P - 1)) {
                g_bar_count = 0;
                __threadfence();
                *(volatile unsigned*)&g_bar_phase = (unsigned)(t + 1);
            }
        }
        if (tid < 32) {
            int b = tid;
            *(float4*)(out + ((size_t)b * TT + t) * HH + jc) = *(float4*)(sh_ho + b * 4);
        }
        if (tid == 0) {
            while (*(volatile unsigned*)&g_bar_phase <= (unsigned)t)
                __nanosleep(32);
            __threadfence();
        }
        __syncthreads();
    }

    // ---- final (h_t, c_t) tail ----
    if (write_tail && tid < 128) {
        int jj = tid >> 5;
        int b  = tid & 31;
        const size_t tail = (size_t)BB * TT * HH;
        out[tail + (size_t)b * HH + jc + jj]                   = sh_ho[b * 4 + jj];
        out[tail + (size_t)BB * HH + (size_t)b * HH + jc + jj] = sh_c[jj * 32 + b];
    }
}

// ---------------- launch ----------------
extern "C" void kernel_launch(void* const* d_in, const int* in_sizes, int n_in,
                              void* d_out, int out_size) {
    const float* x   = (const float*)d_in[0];
    const float* h0  = (const float*)d_in[1];
    const float* c0  = (const float*)d_in[2];
    const float* Wii = (const float*)d_in[3];
    const float* Wif = (const float*)d_in[4];
    const float* Wio = (const float*)d_in[5];
    const float* Wig = (const float*)d_in[6];
    const float* Whi = (const float*)d_in[7];
    const float* Whf = (const float*)d_in[8];
    const float* Who = (const float*)d_in[9];
    const float* Whg = (const float*)d_in[10];
    const float* bi  = (const float*)d_in[11];
    const float* bf_ = (const float*)d_in[12];
    const float* bo  = (const float*)d_in[13];
    const float* bg  = (const float*)d_in[14];
    float* out = (float*)d_out;

    float* xpre;
    cudaGetSymbolAddress((void**)&xpre, g_xpre);

    const size_t smem_bytes = SH_TOTAL_FLOATS * sizeof(float);
    cudaFuncSetAttribute(lstm_persist_kernel,
                         cudaFuncAttributeMaxDynamicSharedMemorySize,
                         (int)smem_bytes);

    const long long tail = (long long)BB * TT * HH;
    const int write_tail = ((long long)out_size >= tail + 2LL * BB * HH) ? 1 : 0;

    gemm_x_kernel<<<dim3(256, 16), 256>>>(x, Wii, Wif, Wio, Wig, bi, bf_, bo, bg, h0, xpre);
    lstm_persist_kernel<<<GRID_P, 512, smem_bytes>>>(
        xpre, Whi, Whf, Who, Whg, c0, out, write_tail);
}

// round 9
// speedup vs baseline: 1.7868x; 1.7868x over previous
#include <cuda_runtime.h>
#include <math.h>

#define BB 32
#define TT 1024
#define II 512
#define HH 512
#define G4 2048      // 4*H
#define GRID_P 128   // persistent CTAs (<=148 -> co-resident, deadlock-free)

typedef unsigned long long u64t;

// ---- packed fp32x2 helpers (Blackwell FFMA2) ----
__device__ __forceinline__ u64t ffma2(u64t a, u64t b, u64t c) {
    u64t d;
    asm("fma.rn.f32x2 %0, %1, %2, %3;" : "=l"(d) : "l"(a), "l"(b), "l"(c));
    return d;
}
__device__ __forceinline__ u64t pack2(float x, float y) {
    u64t d;
    asm("mov.b64 %0, {%1, %2};" : "=l"(d) : "f"(x), "f"(y));
    return d;
}
__device__ __forceinline__ float2 unpack2(u64t v) {
    float2 r;
    asm("mov.b64 {%0, %1}, %2;" : "=f"(r.x), "=f"(r.y) : "l"(v));
    return r;
}
// L2-coherent 16B load (L1 is stale across CTAs; REQUIRED for h double-buffer)
__device__ __forceinline__ void ldcg2(const float* p, u64t& a, u64t& b) {
    asm volatile("ld.global.cg.v2.u64 {%0,%1}, [%2];" : "=l"(a), "=l"(b) : "l"(p));
}

// ---------------- scratch (static device globals; no allocation) ----------------
__device__ float    g_xpre[(size_t)BB * TT * G4];   // [B][T][4H]  256 MB
__device__ float    g_hT[2][HH * BB];               // double-buffered h^T [k][b]
__device__ unsigned g_bar_count;
__device__ unsigned g_bar_phase;

// ---------------- Kernel 1: x_pre = x @ [Wii|Wif|Wio|Wig] + bias ----------------
// (unchanged from the 6181us version)
__global__ __launch_bounds__(256) void gemm_x_kernel(
    const float* __restrict__ X,
    const float* __restrict__ Wii, const float* __restrict__ Wif,
    const float* __restrict__ Wio, const float* __restrict__ Wig,
    const float* __restrict__ bi, const float* __restrict__ bf,
    const float* __restrict__ bo, const float* __restrict__ bg,
    const float* __restrict__ h0,
    float* __restrict__ xpre)
{
    const int mtile = blockIdx.x;          // 0..255
    const int gtile = blockIdx.y;          // 0..15
    const int gate  = gtile >> 2;
    const int j0    = (gtile & 3) * 128;

    if (mtile == 0 && gtile == 0) {
        for (int i = threadIdx.x; i < BB * HH; i += 256) {
            int b = i >> 9;
            int j = i & 511;
            g_hT[0][j * BB + b] = h0[i];
        }
        if (threadIdx.x == 0) { g_bar_count = 0; g_bar_phase = 0; }
    }

    const float* W    = (gate == 0) ? Wii : (gate == 1) ? Wif : (gate == 2) ? Wio : Wig;
    const float* bias = (gate == 0) ? bi  : (gate == 1) ? bf  : (gate == 2) ? bo  : bg;

    __shared__ float As[2][8][132];
    __shared__ float Bs[2][8][128];

    const int tid = threadIdx.x;
    const int tx = tid & 15;
    const int ty = tid >> 4;
    const int m0 = mtile * 128;

    const int a_row = tid >> 1;
    const int a_k   = (tid & 1) * 4;
    const int b_k = tid >> 5;
    const int b_n = (tid & 31) * 4;

    u64t acc2[8][4];
#pragma unroll
    for (int i = 0; i < 8; i++)
#pragma unroll
        for (int j = 0; j < 4; j++) acc2[i][j] = 0ull;

    {
        float4 av = *(const float4*)(X + (size_t)(m0 + a_row) * 512 + a_k);
        As[0][a_k + 0][a_row] = av.x;
        As[0][a_k + 1][a_row] = av.y;
        As[0][a_k + 2][a_row] = av.z;
        As[0][a_k + 3][a_row] = av.w;
        float4 bv = *(const float4*)(W + (size_t)b_k * 512 + j0 + b_n);
        *(float4*)&Bs[0][b_k][b_n] = bv;
    }
    __syncthreads();

    for (int k0 = 0; k0 < 512; k0 += 8) {
        const int cur = (k0 >> 3) & 1;
        const int nxt = cur ^ 1;

        float4 av, bv;
        const bool more = (k0 + 8 < 512);
        if (more) {
            av = *(const float4*)(X + (size_t)(m0 + a_row) * 512 + k0 + 8 + a_k);
            bv = *(const float4*)(W + (size_t)(k0 + 8 + b_k) * 512 + j0 + b_n);
        }

#pragma unroll
        for (int kk = 0; kk < 8; kk++) {
            float4 a0 = *(const float4*)&As[cur][kk][ty * 8];
            float4 a1 = *(const float4*)&As[cur][kk][ty * 8 + 4];
            u64t arr[8];
            arr[0] = pack2(a0.x, a0.x); arr[1] = pack2(a0.y, a0.y);
            arr[2] = pack2(a0.z, a0.z); arr[3] = pack2(a0.w, a0.w);
            arr[4] = pack2(a1.x, a1.x); arr[5] = pack2(a1.y, a1.y);
            arr[6] = pack2(a1.z, a1.z); arr[7] = pack2(a1.w, a1.w);
            ulonglong2 bb0 = *(const ulonglong2*)&Bs[cur][kk][tx * 8];
            ulonglong2 bb1 = *(const ulonglong2*)&Bs[cur][kk][tx * 8 + 4];
            u64t br2[4];
            br2[0] = bb0.x; br2[1] = bb0.y; br2[2] = bb1.x; br2[3] = bb1.y;
#pragma unroll
            for (int i = 0; i < 8; i++)
#pragma unroll
                for (int j = 0; j < 4; j++)
                    acc2[i][j] = ffma2(arr[i], br2[j], acc2[i][j]);
        }

        if (more) {
            As[nxt][a_k + 0][a_row] = av.x;
            As[nxt][a_k + 1][a_row] = av.y;
            As[nxt][a_k + 2][a_row] = av.z;
            As[nxt][a_k + 3][a_row] = av.w;
            *(float4*)&Bs[nxt][b_k][b_n] = bv;
        }
        __syncthreads();
    }

#pragma unroll
    for (int i = 0; i < 8; i++) {
        const size_t m = (size_t)(m0 + ty * 8 + i);
        float* dst = xpre + m * G4 + gate * 512 + j0 + tx * 8;
        float4 o0, o1;
        float2 p0 = unpack2(acc2[i][0]);
        float2 p1 = unpack2(acc2[i][1]);
        float2 p2 = unpack2(acc2[i][2]);
        float2 p3 = unpack2(acc2[i][3]);
        o0.x = p0.x + bias[j0 + tx * 8 + 0];
        o0.y = p0.y + bias[j0 + tx * 8 + 1];
        o0.z = p1.x + bias[j0 + tx * 8 + 2];
        o0.w = p1.y + bias[j0 + tx * 8 + 3];
        o1.x = p2.x + bias[j0 + tx * 8 + 4];
        o1.y = p2.y + bias[j0 + tx * 8 + 5];
        o1.z = p3.x + bias[j0 + tx * 8 + 6];
        o1.w = p3.y + bias[j0 + tx * 8 + 7];
        *(float4*)dst       = o0;
        *(float4*)(dst + 4) = o1;
    }
}

// ---------------- Kernel 2: persistent recurrence (512 threads / 16 warps) -------
// 128 CTAs. CTA owns 4 h-cols jc..jc+3 -> 16 gate-cols.
// Warp w (0..15): k-slice [w*32, w*32+32). Lane = gco*8 + bq:
//   bq  (0..7): 4 batches [bq*4, bq*4+4)
//   gco (0..3): 4 gate-cols [gco*4, gco*4+4)
// Per k per lane: ONE ldcg2 (4 batches; 8 bq span full 128B per warp-instr,
// gco duplicates merge) + one LDS.128 whose two u64 halves are direct f32x2
// weight-PAIR operands (gc,gc+1) — zero weight MOVs; h splats = 8 MOV/k.
// 4 warps/SMSP with round-6-identical traffic.
//
// SMEM layout (floats):
#define SH_W  0                        // w [k][gc]            512*16 = 8192
#define SH_PS (SH_W  + 512*16)         // partials [w][gc][b]  16*16*32 = 8192
#define SH_XS (SH_PS + 16*512)         // xpre [q][b][jj]      4*32*4 = 512
#define SH_C  (SH_XS + 4*32*4)         // cell [jj][b]         128
#define SH_HO (SH_C  + 4*32)           // h out [b][jj]        128
#define SH_TOTAL_FLOATS (SH_HO + 32*4)

extern __shared__ float smem_p[];

__global__ __launch_bounds__(512, 1) void lstm_persist_kernel(
    const float* __restrict__ xpre,
    const float* __restrict__ Whi, const float* __restrict__ Whf,
    const float* __restrict__ Who, const float* __restrict__ Whg,
    const float* __restrict__ c0,
    float* __restrict__ out,
    int write_tail)
{
    float* sh_w  = smem_p + SH_W;
    float* sh_ps = smem_p + SH_PS;
    float* sh_xs = smem_p + SH_XS;
    float* sh_c  = smem_p + SH_C;
    float* sh_ho = smem_p + SH_HO;

    const int tid  = threadIdx.x;
    const int lane = tid & 31;
    const int w    = tid >> 5;              // 0..15
    const int jc   = blockIdx.x * 4;        // h-column base

    const int bq  = lane & 7;               // 0..7 -> 4 batches
    const int gco = lane >> 3;               // 0..3 -> 4 gate-cols

    // ---- one-time: weight slice [k][gc], gc = q*4 + jj ----
    for (int e = tid; e < 512 * 16; e += 512) {
        int k   = e >> 4;
        int gcl = e & 15;
        int q   = gcl >> 2;
        int jj  = gcl & 3;
        const float* Wq = (q == 0) ? Whi : (q == 1) ? Whf : (q == 2) ? Who : Whg;
        sh_w[e] = Wq[(size_t)k * HH + jc + jj];
    }
    if (tid < 128) {
        int jj = tid >> 5;
        int b  = tid & 31;
        sh_c[jj * 32 + b] = c0[b * HH + jc + jj];
    }
    __syncthreads();

    const int kb = w * 32;                   // warp k-slice base (32 k's)

    const int g_jj = tid >> 5;               // gates mapping (tid<128)
    const int g_b  = tid & 31;
    const int x_b = tid >> 2;                // xpre mapping (tid<128)
    const int x_q = tid & 3;

    float4 xnext;
    if (tid < 128)
        xnext = *(const float4*)(xpre + ((size_t)x_b * TT + 0) * G4 + x_q * 512 + jc);

    for (int t = 0; t < TT; ++t) {
        const float* hT_r = g_hT[t & 1];
        float*       hT_w = g_hT[(t + 1) & 1];

        // ---- commit staged xpre; prefetch next ----
        if (tid < 128) {
            *(float4*)(sh_xs + (x_q * 32 + x_b) * 4) = xnext;
            if (t + 1 < TT)
                xnext = *(const float4*)(xpre + ((size_t)x_b * TT + t + 1) * G4 + x_q * 512 + jc);
        }

        // ---- recurrent GEMM slice ----
        // acc[p][bb]: gate-col-pair p (gco*4+2p, +1) x batch bb (b = bq*4+bb)
        u64t acc[2][4];
#pragma unroll
        for (int p = 0; p < 2; p++)
#pragma unroll
            for (int bb = 0; bb < 4; bb++) acc[p][bb] = 0ull;

        const float* hlane = hT_r + (size_t)kb * BB + bq * 4;
        const float* wrow  = sh_w + kb * 16 + gco * 4;

        u64t bufA[8], bufB[8];
        // prefetch chunk 0 (k offsets 0..3): one ldcg2 (4 batches) per k
#pragma unroll
        for (int j = 0; j < 4; j++)
            ldcg2(hlane + j * BB, bufA[j * 2 + 0], bufA[j * 2 + 1]);

#pragma unroll
        for (int c = 0; c < 8; c++) {
            u64t* cur = (c & 1) ? bufB : bufA;
            u64t* nxt = (c & 1) ? bufA : bufB;
            if (c < 7) {
                const float* hp2 = hlane + (size_t)(c + 1) * 4 * BB;
#pragma unroll
                for (int j = 0; j < 4; j++)
                    ldcg2(hp2 + j * BB, nxt[j * 2 + 0], nxt[j * 2 + 1]);
            }
#pragma unroll
            for (int j = 0; j < 4; j++) {
                const int kk = c * 4 + j;
                // one LDS.128: (w_gc0,w_gc1) and (w_gc2,w_gc3) as READY f32x2 pairs
                ulonglong2 wv = *(const ulonglong2*)(wrow + kk * 16);
                float2 hA = unpack2(cur[j * 2 + 0]);   // h_b0, h_b1
                float2 hB = unpack2(cur[j * 2 + 1]);   // h_b2, h_b3
                u64t hs0 = pack2(hA.x, hA.x);
                u64t hs1 = pack2(hA.y, hA.y);
                u64t hs2 = pack2(hB.x, hB.x);
                u64t hs3 = pack2(hB.y, hB.y);
                acc[0][0] = ffma2(hs0, wv.x, acc[0][0]);
                acc[1][0] = ffma2(hs0, wv.y, acc[1][0]);
                acc[0][1] = ffma2(hs1, wv.x, acc[0][1]);
                acc[1][1] = ffma2(hs1, wv.y, acc[1][1]);
                acc[0][2] = ffma2(hs2, wv.x, acc[0][2]);
                acc[1][2] = ffma2(hs2, wv.y, acc[1][2]);
                acc[0][3] = ffma2(hs3, wv.x, acc[0][3]);
                acc[1][3] = ffma2(hs3, wv.y, acc[1][3]);
            }
        }

        // ---- write partials: slot = warp; layout [gc][b] (round-6 gates compat)
        {
            float* ps = sh_ps + (size_t)w * 512;
#pragma unroll
            for (int p = 0; p < 2; p++) {
                const int gc0 = gco * 4 + p * 2;
#pragma unroll
                for (int bb = 0; bb < 4; bb++) {
                    float2 v = unpack2(acc[p][bb]);
                    ps[gc0 * 32 + bq * 4 + bb]       = v.x;
                    ps[(gc0 + 1) * 32 + bq * 4 + bb] = v.y;
                }
            }
        }
        __syncthreads();

        // ---- gates + state update (128 threads: jj x b) ----
        if (tid < 128) {
            const int jj = g_jj, b = g_b;
            float v[4];
#pragma unroll
            for (int q = 0; q < 4; q++) {
                float s = sh_xs[(q * 32 + b) * 4 + jj];
                const int gc = q * 4 + jj;
#pragma unroll
                for (int ws16 = 0; ws16 < 16; ws16++)
                    s += sh_ps[ws16 * 512 + gc * 32 + b];
                v[q] = s;
            }
            float it = 1.0f / (1.0f + expf(-v[0]));
            float ft = 1.0f / (1.0f + expf(-v[1]));
            float ot = 1.0f / (1.0f + expf(-v[2]));
            float gt = tanhf(v[3]);
            float cn = ft * sh_c[jj * 32 + b] + it * gt;
            float hn = ot * tanhf(cn);
            sh_c[jj * 32 + b] = cn;
            sh_ho[b * 4 + jj] = hn;
            hT_w[(jc + jj) * BB + b] = hn;     // coalesced 128B per jj
        }
        __syncthreads();

        // ---- arrival, output write, poll (warp 0) ----
        if (tid == 0) {
            __threadfence();
            unsigned a = atomicAdd(&g_bar_count, 1u);
            if (a == (unsigned)(GRID_P - 1)) {
                g_bar_count = 0;
                __threadfence();
                *(volatile unsigned*)&g_bar_phase = (unsigned)(t + 1);
            }
        }
        if (tid < 32) {
            int b = tid;
            *(float4*)(out + ((size_t)b * TT + t) * HH + jc) = *(float4*)(sh_ho + b * 4);
        }
        if (tid == 0) {
            while (*(volatile unsigned*)&g_bar_phase <= (unsigned)t)
                __nanosleep(32);
            __threadfence();
        }
        __syncthreads();
    }

    // ---- final (h_t, c_t) tail ----
    if (write_tail && tid < 128) {
        int jj = tid >> 5;
        int b  = tid & 31;
        const size_t tail = (size_t)BB * TT * HH;
        out[tail + (size_t)b * HH + jc + jj]                   = sh_ho[b * 4 + jj];
        out[tail + (size_t)BB * HH + (size_t)b * HH + jc + jj] = sh_c[jj * 32 + b];
    }
}

// ---------------- launch ----------------
extern "C" void kernel_launch(void* const* d_in, const int* in_sizes, int n_in,
                              void* d_out, int out_size) {
    const float* x   = (const float*)d_in[0];
    const float* h0  = (const float*)d_in[1];
    const float* c0  = (const float*)d_in[2];
    const float* Wii = (const float*)d_in[3];
    const float* Wif = (const float*)d_in[4];
    const float* Wio = (const float*)d_in[5];
    const float* Wig = (const float*)d_in[6];
    const float* Whi = (const float*)d_in[7];
    const float* Whf = (const float*)d_in[8];
    const float* Who = (const float*)d_in[9];
    const float* Whg = (const float*)d_in[10];
    const float* bi  = (const float*)d_in[11];
    const float* bf_ = (const float*)d_in[12];
    const float* bo  = (const float*)d_in[13];
    const float* bg  = (const float*)d_in[14];
    float* out = (float*)d_out;

    float* xpre;
    cudaGetSymbolAddress((void**)&xpre, g_xpre);

    const size_t smem_bytes = SH_TOTAL_FLOATS * sizeof(float);
    cudaFuncSetAttribute(lstm_persist_kernel,
                         cudaFuncAttributeMaxDynamicSharedMemorySize,
                         (int)smem_bytes);

    const long long tail = (long long)BB * TT * HH;
    const int write_tail = ((long long)out_size >= tail + 2LL * BB * HH) ? 1 : 0;

    gemm_x_kernel<<<dim3(256, 16), 256>>>(x, Wii, Wif, Wio, Wig, bi, bf_, bo, bg, h0, xpre);
    lstm_persist_kernel<<<GRID_P, 512, smem_bytes>>>(
        xpre, Whi, Whf, Who, Whg, c0, out, write_tail);
}

// round 10
// speedup vs baseline: 1.9681x; 1.1015x over previous
#include <cuda_runtime.h>
#include <math.h>

#define BB 32
#define TT 1024
#define II 512
#define HH 512
#define G4 2048      // 4*H
#define GRID_P 128   // persistent CTAs (<=148 -> co-resident, deadlock-free)

typedef unsigned long long u64t;

// ---- packed fp32x2 helpers (Blackwell FFMA2) ----
__device__ __forceinline__ u64t ffma2(u64t a, u64t b, u64t c) {
    u64t d;
    asm("fma.rn.f32x2 %0, %1, %2, %3;" : "=l"(d) : "l"(a), "l"(b), "l"(c));
    return d;
}
__device__ __forceinline__ u64t pack2(float x, float y) {
    u64t d;
    asm("mov.b64 %0, {%1, %2};" : "=l"(d) : "f"(x), "f"(y));
    return d;
}
__device__ __forceinline__ float2 unpack2(u64t v) {
    float2 r;
    asm("mov.b64 {%0, %1}, %2;" : "=f"(r.x), "=f"(r.y) : "l"(v));
    return r;
}
// L2-coherent 16B load (L1 is stale across CTAs; REQUIRED for h double-buffer)
__device__ __forceinline__ void ldcg2(const float* p, u64t& a, u64t& b) {
    asm volatile("ld.global.cg.v2.u64 {%0,%1}, [%2];" : "=l"(a), "=l"(b) : "l"(p));
}

// ---------------- scratch (static device globals; no allocation) ----------------
__device__ float    g_xpre[(size_t)BB * TT * G4];   // [B][T][4H]  256 MB
__device__ float    g_hT[2][HH * BB];               // double-buffered h^T [k][b]
__device__ unsigned g_bar_count;
__device__ unsigned g_bar_phase;

// ---------------- Kernel 1: x_pre = x @ [Wii|Wif|Wio|Wig] + bias ----------------
// (unchanged from the 6177us version)
__global__ __launch_bounds__(256) void gemm_x_kernel(
    const float* __restrict__ X,
    const float* __restrict__ Wii, const float* __restrict__ Wif,
    const float* __restrict__ Wio, const float* __restrict__ Wig,
    const float* __restrict__ bi, const float* __restrict__ bf,
    const float* __restrict__ bo, const float* __restrict__ bg,
    const float* __restrict__ h0,
    float* __restrict__ xpre)
{
    const int mtile = blockIdx.x;          // 0..255
    const int gtile = blockIdx.y;          // 0..15
    const int gate  = gtile >> 2;
    const int j0    = (gtile & 3) * 128;

    if (mtile == 0 && gtile == 0) {
        for (int i = threadIdx.x; i < BB * HH; i += 256) {
            int b = i >> 9;
            int j = i & 511;
            g_hT[0][j * BB + b] = h0[i];
        }
        if (threadIdx.x == 0) { g_bar_count = 0; g_bar_phase = 0; }
    }

    const float* W    = (gate == 0) ? Wii : (gate == 1) ? Wif : (gate == 2) ? Wio : Wig;
    const float* bias = (gate == 0) ? bi  : (gate == 1) ? bf  : (gate == 2) ? bo  : bg;

    __shared__ float As[2][8][132];
    __shared__ float Bs[2][8][128];

    const int tid = threadIdx.x;
    const int tx = tid & 15;
    const int ty = tid >> 4;
    const int m0 = mtile * 128;

    const int a_row = tid >> 1;
    const int a_k   = (tid & 1) * 4;
    const int b_k = tid >> 5;
    const int b_n = (tid & 31) * 4;

    u64t acc2[8][4];
#pragma unroll
    for (int i = 0; i < 8; i++)
#pragma unroll
        for (int j = 0; j < 4; j++) acc2[i][j] = 0ull;

    {
        float4 av = *(const float4*)(X + (size_t)(m0 + a_row) * 512 + a_k);
        As[0][a_k + 0][a_row] = av.x;
        As[0][a_k + 1][a_row] = av.y;
        As[0][a_k + 2][a_row] = av.z;
        As[0][a_k + 3][a_row] = av.w;
        float4 bv = *(const float4*)(W + (size_t)b_k * 512 + j0 + b_n);
        *(float4*)&Bs[0][b_k][b_n] = bv;
    }
    __syncthreads();

    for (int k0 = 0; k0 < 512; k0 += 8) {
        const int cur = (k0 >> 3) & 1;
        const int nxt = cur ^ 1;

        float4 av, bv;
        const bool more = (k0 + 8 < 512);
        if (more) {
            av = *(const float4*)(X + (size_t)(m0 + a_row) * 512 + k0 + 8 + a_k);
            bv = *(const float4*)(W + (size_t)(k0 + 8 + b_k) * 512 + j0 + b_n);
        }

#pragma unroll
        for (int kk = 0; kk < 8; kk++) {
            float4 a0 = *(const float4*)&As[cur][kk][ty * 8];
            float4 a1 = *(const float4*)&As[cur][kk][ty * 8 + 4];
            u64t arr[8];
            arr[0] = pack2(a0.x, a0.x); arr[1] = pack2(a0.y, a0.y);
            arr[2] = pack2(a0.z, a0.z); arr[3] = pack2(a0.w, a0.w);
            arr[4] = pack2(a1.x, a1.x); arr[5] = pack2(a1.y, a1.y);
            arr[6] = pack2(a1.z, a1.z); arr[7] = pack2(a1.w, a1.w);
            ulonglong2 bb0 = *(const ulonglong2*)&Bs[cur][kk][tx * 8];
            ulonglong2 bb1 = *(const ulonglong2*)&Bs[cur][kk][tx * 8 + 4];
            u64t br2[4];
            br2[0] = bb0.x; br2[1] = bb0.y; br2[2] = bb1.x; br2[3] = bb1.y;
#pragma unroll
            for (int i = 0; i < 8; i++)
#pragma unroll
                for (int j = 0; j < 4; j++)
                    acc2[i][j] = ffma2(arr[i], br2[j], acc2[i][j]);
        }

        if (more) {
            As[nxt][a_k + 0][a_row] = av.x;
            As[nxt][a_k + 1][a_row] = av.y;
            As[nxt][a_k + 2][a_row] = av.z;
            As[nxt][a_k + 3][a_row] = av.w;
            *(float4*)&Bs[nxt][b_k][b_n] = bv;
        }
        __syncthreads();
    }

#pragma unroll
    for (int i = 0; i < 8; i++) {
        const size_t m = (size_t)(m0 + ty * 8 + i);
        float* dst = xpre + m * G4 + gate * 512 + j0 + tx * 8;
        float4 o0, o1;
        float2 p0 = unpack2(acc2[i][0]);
        float2 p1 = unpack2(acc2[i][1]);
        float2 p2 = unpack2(acc2[i][2]);
        float2 p3 = unpack2(acc2[i][3]);
        o0.x = p0.x + bias[j0 + tx * 8 + 0];
        o0.y = p0.y + bias[j0 + tx * 8 + 1];
        o0.z = p1.x + bias[j0 + tx * 8 + 2];
        o0.w = p1.y + bias[j0 + tx * 8 + 3];
        o1.x = p2.x + bias[j0 + tx * 8 + 4];
        o1.y = p2.y + bias[j0 + tx * 8 + 5];
        o1.z = p3.x + bias[j0 + tx * 8 + 6];
        o1.w = p3.y + bias[j0 + tx * 8 + 7];
        *(float4*)dst       = o0;
        *(float4*)(dst + 4) = o1;
    }
}

// ---------------- Kernel 2: persistent recurrence (512 threads / 16 warps) -------
// Same GEMM tiling as the 6177us version (round 9). Changes:
//  - release/acquire barrier (no membar.gpu); releasing CTA skips its own poll
//  - gates reduction+activation parallelized over all 512 threads (phase A),
//    then 128-thread c/h update (phase B)
//
// SMEM layout (floats):
#define SH_W  0                        // w [k][gc]            512*16 = 8192
#define SH_PS (SH_W  + 512*16)         // partials [w][gc][b]  16*16*32 = 8192
#define SH_XS (SH_PS + 16*512)         // xpre [q][b][jj]      4*32*4 = 512
#define SH_C  (SH_XS + 4*32*4)         // cell [jj][b]         128
#define SH_G  (SH_C  + 4*32)           // activated gates [gc][b] 16*32 = 512
#define SH_HO (SH_G  + 16*32)          // h out [b][jj]        128
#define SH_TOTAL_FLOATS (SH_HO + 32*4)

extern __shared__ float smem_p[];

__global__ __launch_bounds__(512, 1) void lstm_persist_kernel(
    const float* __restrict__ xpre,
    const float* __restrict__ Whi, const float* __restrict__ Whf,
    const float* __restrict__ Who, const float* __restrict__ Whg,
    const float* __restrict__ c0,
    float* __restrict__ out,
    int write_tail)
{
    float* sh_w  = smem_p + SH_W;
    float* sh_ps = smem_p + SH_PS;
    float* sh_xs = smem_p + SH_XS;
    float* sh_c  = smem_p + SH_C;
    float* sh_g  = smem_p + SH_G;
    float* sh_ho = smem_p + SH_HO;

    const int tid  = threadIdx.x;
    const int lane = tid & 31;
    const int w    = tid >> 5;              // 0..15
    const int jc   = blockIdx.x * 4;        // h-column base

    const int bq  = lane & 7;               // 0..7 -> 4 batches
    const int gco = lane >> 3;               // 0..3 -> 4 gate-cols

    // ---- one-time: weight slice [k][gc], gc = q*4 + jj ----
    for (int e = tid; e < 512 * 16; e += 512) {
        int k   = e >> 4;
        int gcl = e & 15;
        int q   = gcl >> 2;
        int jj  = gcl & 3;
        const float* Wq = (q == 0) ? Whi : (q == 1) ? Whf : (q == 2) ? Who : Whg;
        sh_w[e] = Wq[(size_t)k * HH + jc + jj];
    }
    if (tid < 128) {
        int jj = tid >> 5;
        int b  = tid & 31;
        sh_c[jj * 32 + b] = c0[b * HH + jc + jj];
    }
    __syncthreads();

    const int kb = w * 32;                   // warp k-slice base (32 k's)

    // gates phase A mapping: thread -> (gate-col gc 0..15, batch b 0..31)
    const int a_gc = tid >> 5;               // == w (warp-uniform activation!)
    const int a_b  = tid & 31;
    const int a_q  = a_gc >> 2;
    const int a_jj = a_gc & 3;
    // gates phase B mapping (tid<128)
    const int g_jj = tid >> 5;
    const int g_b  = tid & 31;
    // xpre mapping (tid<128)
    const int x_b = tid >> 2;
    const int x_q = tid & 3;

    float4 xnext;
    if (tid < 128)
        xnext = *(const float4*)(xpre + ((size_t)x_b * TT + 0) * G4 + x_q * 512 + jc);

    unsigned* bar_count = &g_bar_count;
    unsigned* bar_phase = &g_bar_phase;

    for (int t = 0; t < TT; ++t) {
        const float* hT_r = g_hT[t & 1];
        float*       hT_w = g_hT[(t + 1) & 1];

        // ---- commit staged xpre; prefetch next ----
        if (tid < 128) {
            *(float4*)(sh_xs + (x_q * 32 + x_b) * 4) = xnext;
            if (t + 1 < TT)
                xnext = *(const float4*)(xpre + ((size_t)x_b * TT + t + 1) * G4 + x_q * 512 + jc);
        }

        // ---- recurrent GEMM slice (identical to round 9) ----
        u64t acc[2][4];
#pragma unroll
        for (int p = 0; p < 2; p++)
#pragma unroll
            for (int bb = 0; bb < 4; bb++) acc[p][bb] = 0ull;

        const float* hlane = hT_r + (size_t)kb * BB + bq * 4;
        const float* wrow  = sh_w + kb * 16 + gco * 4;

        u64t bufA[8], bufB[8];
#pragma unroll
        for (int j = 0; j < 4; j++)
            ldcg2(hlane + j * BB, bufA[j * 2 + 0], bufA[j * 2 + 1]);

#pragma unroll
        for (int c = 0; c < 8; c++) {
            u64t* cur = (c & 1) ? bufB : bufA;
            u64t* nxt = (c & 1) ? bufA : bufB;
            if (c < 7) {
                const float* hp2 = hlane + (size_t)(c + 1) * 4 * BB;
#pragma unroll
                for (int j = 0; j < 4; j++)
                    ldcg2(hp2 + j * BB, nxt[j * 2 + 0], nxt[j * 2 + 1]);
            }
#pragma unroll
            for (int j = 0; j < 4; j++) {
                const int kk = c * 4 + j;
                ulonglong2 wv = *(const ulonglong2*)(wrow + kk * 16);
                float2 hA = unpack2(cur[j * 2 + 0]);
                float2 hB = unpack2(cur[j * 2 + 1]);
                u64t hs0 = pack2(hA.x, hA.x);
                u64t hs1 = pack2(hA.y, hA.y);
                u64t hs2 = pack2(hB.x, hB.x);
                u64t hs3 = pack2(hB.y, hB.y);
                acc[0][0] = ffma2(hs0, wv.x, acc[0][0]);
                acc[1][0] = ffma2(hs0, wv.y, acc[1][0]);
                acc[0][1] = ffma2(hs1, wv.x, acc[0][1]);
                acc[1][1] = ffma2(hs1, wv.y, acc[1][1]);
                acc[0][2] = ffma2(hs2, wv.x, acc[0][2]);
                acc[1][2] = ffma2(hs2, wv.y, acc[1][2]);
                acc[0][3] = ffma2(hs3, wv.x, acc[0][3]);
                acc[1][3] = ffma2(hs3, wv.y, acc[1][3]);
            }
        }

        // ---- write partials: slot = warp; layout [gc][b] ----
        {
            float* ps = sh_ps + (size_t)w * 512;
#pragma unroll
            for (int p = 0; p < 2; p++) {
                const int gc0 = gco * 4 + p * 2;
#pragma unroll
                for (int bb = 0; bb < 4; bb++) {
                    float2 v = unpack2(acc[p][bb]);
                    ps[gc0 * 32 + bq * 4 + bb]       = v.x;
                    ps[(gc0 + 1) * 32 + bq * 4 + bb] = v.y;
                }
            }
        }
        __syncthreads();

        // ---- gates phase A (ALL 512 threads): reduce + activation ----
        {
            float s = sh_xs[(a_q * 32 + a_b) * 4 + a_jj];
            const int off = a_gc * 32 + a_b;
#pragma unroll
            for (int ws16 = 0; ws16 < 16; ws16++)
                s += sh_ps[ws16 * 512 + off];
            float g;
            if (a_q == 3)      g = tanhf(s);
            else               g = __fdividef(1.0f, 1.0f + __expf(-s));
            sh_g[off] = g;
        }
        __syncthreads();

        // ---- gates phase B (128 threads): c/h update ----
        if (tid < 128) {
            const int jj = g_jj, b = g_b;
            float it = sh_g[(0 * 4 + jj) * 32 + b];
            float ft = sh_g[(1 * 4 + jj) * 32 + b];
            float ot = sh_g[(2 * 4 + jj) * 32 + b];
            float gt = sh_g[(3 * 4 + jj) * 32 + b];
            float cn = ft * sh_c[jj * 32 + b] + it * gt;
            float hn = ot * tanhf(cn);
            sh_c[jj * 32 + b] = cn;
            sh_ho[b * 4 + jj] = hn;
            hT_w[(jc + jj) * BB + b] = hn;     // coalesced 128B per jj
        }
        __syncthreads();

        // ---- barrier: release arrival; releasing CTA skips its poll ----
        bool releaser = false;
        if (tid == 0) {
            unsigned a;
            asm volatile("atom.release.gpu.global.add.u32 %0, [%1], %2;"
                         : "=r"(a) : "l"(bar_count), "r"(1u) : "memory");
            if (a == (unsigned)(GRID_P - 1)) {
                releaser = true;
                *bar_count = 0;    // ordered before the release-store below
                asm volatile("st.release.gpu.global.u32 [%0], %1;"
                             :: "l"(bar_phase), "r"((unsigned)(t + 1)) : "memory");
            }
        }
        if (tid < 32) {
            int b = tid;
            *(float4*)(out + ((size_t)b * TT + t) * HH + jc) = *(float4*)(sh_ho + b * 4);
        }
        if (tid == 0 && !releaser) {
            unsigned ph;
            for (;;) {
                asm volatile("ld.acquire.gpu.global.u32 %0, [%1];"
                             : "=r"(ph) : "l"(bar_phase) : "memory");
                if ((int)ph > t) break;
                __nanosleep(32);
            }
        }
        __syncthreads();
    }

    // ---- final (h_t, c_t) tail ----
    if (write_tail && tid < 128) {
        int jj = tid >> 5;
        int b  = tid & 31;
        const size_t tail = (size_t)BB * TT * HH;
        out[tail + (size_t)b * HH + jc + jj]                   = sh_ho[b * 4 + jj];
        out[tail + (size_t)BB * HH + (size_t)b * HH + jc + jj] = sh_c[jj * 32 + b];
    }
}

// ---------------- launch ----------------
extern "C" void kernel_launch(void* const* d_in, const int* in_sizes, int n_in,
                              void* d_out, int out_size) {
    const float* x   = (const float*)d_in[0];
    const float* h0  = (const float*)d_in[1];
    const float* c0  = (const float*)d_in[2];
    const float* Wii = (const float*)d_in[3];
    const float* Wif = (const float*)d_in[4];
    const float* Wio = (const float*)d_in[5];
    const float* Wig = (const float*)d_in[6];
    const float* Whi = (const float*)d_in[7];
    const float* Whf = (const float*)d_in[8];
    const float* Who = (const float*)d_in[9];
    const float* Whg = (const float*)d_in[10];
    const float* bi  = (const float*)d_in[11];
    const float* bf_ = (const float*)d_in[12];
    const float* bo  = (const float*)d_in[13];
    const float* bg  = (const float*)d_in[14];
    float* out = (float*)d_out;

    float* xpre;
    cudaGetSymbolAddress((void**)&xpre, g_xpre);

    const size_t smem_bytes = SH_TOTAL_FLOATS * sizeof(float);
    cudaFuncSetAttribute(lstm_persist_kernel,
                         cudaFuncAttributeMaxDynamicSharedMemorySize,
                         (int)smem_bytes);

    const long long tail = (long long)BB * TT * HH;
    const int write_tail = ((long long)out_size >= tail + 2LL * BB * HH) ? 1 : 0;

    gemm_x_kernel<<<dim3(256, 16), 256>>>(x, Wii, Wif, Wio, Wig, bi, bf_, bo, bg, h0, xpre);
    lstm_persist_kernel<<<GRID_P, 512, smem_bytes>>>(
        xpre, Whi, Whf, Who, Whg, c0, out, write_tail);
}